// round 11
// baseline (speedup 1.0000x reference)
#include <cuda_runtime.h>
#include <math.h>
#include <cstdint>

#define NNODES 20000
#define NEDGES 640000
#define NSZ 128
#define ESZ 20
#define CUTF 5.0f
#define PIF 3.14159265358979f

// ---------------- device scratch (precomputed node-side gate payloads) ----
__device__ float g_dsv[NNODES * 384];   // nsv  . soSV   [node][3][128]
__device__ float g_sev[NNODES * 128];   // soEV          [node][128]
__device__ float g_cns[NNODES * 128];   // nss  . soNS   [node][128]

typedef unsigned long long u64;

// ---------------- helpers ----------------
__device__ __forceinline__ void fma2(u64& d, u64 a, u64 b) {
    asm("fma.rn.f32x2 %0, %1, %2, %0;" : "+l"(d) : "l"(a), "l"(b));
}
__device__ __forceinline__ u64 pack2(float x) {
    u64 r; asm("mov.b64 %0, {%1, %1};" : "=l"(r) : "f"(x)); return r;
}
__device__ __forceinline__ float2 unpack2(u64 a) {
    float2 f; asm("mov.b64 {%0, %1}, %2;" : "=f"(f.x), "=f"(f.y) : "l"(a));
    return f;
}
__device__ __forceinline__ float4 f4_mul(float4 a, float4 b) {
    return make_float4(a.x*b.x, a.y*b.y, a.z*b.z, a.w*b.w);
}
__device__ __forceinline__ void red1(float* p, float v) {
    asm volatile("red.global.add.f32 [%0], %1;" :: "l"(p), "f"(v) : "memory");
}

// ---------------------------------------------------------------------------
// Kernel 1: node MLP + fused gate payloads (round-10 proven: 96KB, 2 blk/SM)
// ---------------------------------------------------------------------------
#define NB 64

__global__ void __launch_bounds__(256, 2) node_mlp(
    const float4* __restrict__ nss4, const float4* __restrict__ nsv4,
    const float* __restrict__ W1, const float* __restrict__ b1,
    const float* __restrict__ W2, const float* __restrict__ b2,
    float4* __restrict__ out)
{
    extern __shared__ float sm[];
    float* sW = sm;              // 8192 (k-half tile)
    float* sX = sm + 8192;       // 8192
    float* sH = sX + 8192;       // 8192

    const int tid = threadIdx.x;
    const int n0 = blockIdx.x * NB;

    // init-out fold
    {
        const float4* nssb = nss4 + (size_t)n0 * 32;
        float4* outS = out + (size_t)n0 * 32;
        for (int i = tid; i < NB * 32; i += 256)
            if (n0 + (i >> 5) < NNODES) outS[i] = nssb[i];
        const float4* nsvb = nsv4 + (size_t)n0 * 96;
        float4* outV = out + (size_t)NNODES * 32 + (size_t)n0 * 96;
        for (int i = tid; i < NB * 96; i += 256)
            if (n0 + i / 96 < NNODES) outV[i] = nsvb[i];
    }

    for (int i = tid; i < NB * 32; i += 256) {
        int n = n0 + (i >> 5);
        ((float4*)sX)[i] = (n < NNODES) ? nss4[(size_t)n * 32 + (i & 31)]
                                        : make_float4(0.f, 0.f, 0.f, 0.f);
    }
    __syncthreads();

    const int tx = tid & 31, ty = tid >> 5;
    const int c0 = tx * 4;

    u64 acc[8][2];

    // phase 1: H = silu(X @ W1 + b1), two k-halves
    #pragma unroll
    for (int i = 0; i < 8; i++) { acc[i][0] = 0ull; acc[i][1] = 0ull; }
    for (int h = 0; h < 2; h++) {
        for (int i = tid; i < 2048; i += 256)
            ((float4*)sW)[i] = ((const float4*)W1)[h * 2048 + i];
        __syncthreads();
        #pragma unroll 4
        for (int k = 0; k < 64; k += 4) {
            const ulonglong2 w0 = *(const ulonglong2*)&sW[(k + 0) * 128 + c0];
            const ulonglong2 w1 = *(const ulonglong2*)&sW[(k + 1) * 128 + c0];
            const ulonglong2 w2 = *(const ulonglong2*)&sW[(k + 2) * 128 + c0];
            const ulonglong2 w3 = *(const ulonglong2*)&sW[(k + 3) * 128 + c0];
            #pragma unroll
            for (int i = 0; i < 8; i++) {
                const float4 xv = *(const float4*)&sX[(ty * 8 + i) * 128 + h * 64 + k];
                const u64 x0 = pack2(xv.x), x1 = pack2(xv.y);
                const u64 x2 = pack2(xv.z), x3 = pack2(xv.w);
                fma2(acc[i][0], x0, w0.x); fma2(acc[i][1], x0, w0.y);
                fma2(acc[i][0], x1, w1.x); fma2(acc[i][1], x1, w1.y);
                fma2(acc[i][0], x2, w2.x); fma2(acc[i][1], x2, w2.y);
                fma2(acc[i][0], x3, w3.x); fma2(acc[i][1], x3, w3.y);
            }
        }
        __syncthreads();
    }
    {
        const float4 bb = __ldg((const float4*)&b1[c0]);
        #pragma unroll
        for (int i = 0; i < 8; i++) {
            const float2 lo = unpack2(acc[i][0]);
            const float2 hi = unpack2(acc[i][1]);
            float4 h = make_float4(lo.x + bb.x, lo.y + bb.y, hi.x + bb.z, hi.y + bb.w);
            h.x = h.x / (1.f + __expf(-h.x));
            h.y = h.y / (1.f + __expf(-h.y));
            h.z = h.z / (1.f + __expf(-h.z));
            h.w = h.w / (1.f + __expf(-h.w));
            *(float4*)&sH[(ty * 8 + i) * 128 + c0] = h;
        }
    }
    __syncthreads();

    // phase 2: three output tiles
    for (int t = 0; t < 3; t++) {
        #pragma unroll
        for (int i = 0; i < 8; i++) { acc[i][0] = 0ull; acc[i][1] = 0ull; }
        for (int h = 0; h < 2; h++) {
            for (int i = tid; i < 2048; i += 256) {
                int k = i >> 5, jj = i & 31;
                ((float4*)sW)[i] =
                    *(const float4*)&W2[(size_t)(h * 64 + k) * 384 + t * 128 + jj * 4];
            }
            __syncthreads();
            #pragma unroll 4
            for (int k = 0; k < 64; k += 4) {
                const ulonglong2 w0 = *(const ulonglong2*)&sW[(k + 0) * 128 + c0];
                const ulonglong2 w1 = *(const ulonglong2*)&sW[(k + 1) * 128 + c0];
                const ulonglong2 w2 = *(const ulonglong2*)&sW[(k + 2) * 128 + c0];
                const ulonglong2 w3 = *(const ulonglong2*)&sW[(k + 3) * 128 + c0];
                #pragma unroll
                for (int i = 0; i < 8; i++) {
                    const float4 xv = *(const float4*)&sH[(ty * 8 + i) * 128 + h * 64 + k];
                    const u64 x0 = pack2(xv.x), x1 = pack2(xv.y);
                    const u64 x2 = pack2(xv.z), x3 = pack2(xv.w);
                    fma2(acc[i][0], x0, w0.x); fma2(acc[i][1], x0, w0.y);
                    fma2(acc[i][0], x1, w1.x); fma2(acc[i][1], x1, w1.y);
                    fma2(acc[i][0], x2, w2.x); fma2(acc[i][1], x2, w2.y);
                    fma2(acc[i][0], x3, w3.x); fma2(acc[i][1], x3, w3.y);
                }
            }
            __syncthreads();
        }
        const float4 bb = __ldg((const float4*)&b2[t * 128 + c0]);
        #pragma unroll
        for (int i = 0; i < 8; i++) {
            const int ln = ty * 8 + i;
            const int n = n0 + ln;
            if (n >= NNODES) continue;
            const float2 lo = unpack2(acc[i][0]);
            const float2 hi = unpack2(acc[i][1]);
            const float4 so = make_float4(lo.x + bb.x, lo.y + bb.y,
                                          hi.x + bb.z, hi.y + bb.w);
            if (t == 0) {
                #pragma unroll
                for (int d3 = 0; d3 < 3; d3++) {
                    const float4 xv =
                        __ldg((const float4*)((const float*)nsv4 +
                                              (size_t)n * 384 + d3 * 128 + c0));
                    *(float4*)&g_dsv[(size_t)n * 384 + d3 * 128 + c0] =
                        f4_mul(xv, so);
                }
            } else if (t == 1) {
                *(float4*)&g_sev[(size_t)n * 128 + c0] = so;
            } else {
                const float4 xs = *(const float4*)&sX[ln * 128 + c0];
                *(float4*)&g_cns[(size_t)n * 128 + c0] = f4_mul(xs, so);
            }
        }
    }
}

// ---------------------------------------------------------------------------
// Kernel 2: block-cooperative edge kernel. 16 edges/iter, 128 threads.
// Warp w owns column (w*32+lane) of each 128-col group. f32x2 lanes = edge
// pairs. W via per-lane scalar LDS (1 wf); ES pair-transposed broadcast.
// ---------------------------------------------------------------------------
#define EPB 16

__global__ void __launch_bounds__(128, 5) edge_kernel(
    const float* __restrict__ edge_state, const float* __restrict__ edge_vector,
    const float* __restrict__ edge_distance, const int* __restrict__ edges,
    const float* __restrict__ Wf, const float* __restrict__ bf,
    float* __restrict__ out)
{
    __shared__ float sWf[ESZ * 384];
    __shared__ float sbf[384];
    __shared__ __align__(16) float sESp[8 * 10 * 4];  // [pair][kduo] float4
    __shared__ float4 sMeta[EPB];
    __shared__ int2  sIdx[EPB];

    const int tid = threadIdx.x;
    for (int i = tid; i < ESZ * 384 / 4; i += 128)
        ((float4*)sWf)[i] = ((const float4*)Wf)[i];
    for (int i = tid; i < 96; i += 128)
        ((float4*)sbf)[i] = ((const float4*)bf)[i];
    __syncthreads();

    const int lane = tid & 31;
    const int wid  = tid >> 5;
    const int c    = wid * 32 + lane;      // column within each 128-group
    const u64 bS = pack2(sbf[c]);
    const u64 bE = pack2(sbf[128 + c]);
    const u64 bN = pack2(sbf[256 + c]);

    float* __restrict__ outS = out;
    float* __restrict__ outV = out + (size_t)NNODES * NSZ;

    for (int t0 = blockIdx.x * EPB; t0 < NEDGES; t0 += gridDim.x * EPB) {
        // ---- stage: ES pair-transposed + per-edge meta ----
        if (tid < 80) {
            const int p = tid / 10, kd = tid % 10;
            const float2 a =
                __ldg((const float2*)&edge_state[(size_t)(t0 + 2 * p) * ESZ + 2 * kd]);
            const float2 b =
                __ldg((const float2*)&edge_state[(size_t)(t0 + 2 * p + 1) * ESZ + 2 * kd]);
            ((float4*)sESp)[p * 10 + kd] = make_float4(a.x, b.x, a.y, b.y);
        }
        if (tid < EPB) {
            const int ed = t0 + tid;
            sIdx[tid] = __ldg((const int2*)&edges[2 * ed]);
            const float d = __ldg(&edge_distance[ed]);
            const float cu = (d < CUTF)
                ? 0.5f * (__cosf(PIF * d * (1.0f / CUTF)) + 1.0f) : 0.0f;
            const float v0 = __ldg(&edge_vector[3 * ed]);
            const float v1 = __ldg(&edge_vector[3 * ed + 1]);
            const float v2 = __ldg(&edge_vector[3 * ed + 2]);
            const float inv = 1.0f / fmaxf(sqrtf(v0*v0 + v1*v1 + v2*v2), 1e-12f);
            sMeta[tid] = make_float4(v0 * inv, v1 * inv, v2 * inv, cu);
        }
        __syncthreads();

        // ---- filter GEMM: 8 edge-pairs x 3 groups, f32x2 over edge pairs ----
        u64 acc[8][3];
        #pragma unroll
        for (int p = 0; p < 8; p++) { acc[p][0] = bS; acc[p][1] = bE; acc[p][2] = bN; }
        #pragma unroll
        for (int kd = 0; kd < 10; kd++) {
            const int k0 = 2 * kd;
            const u64 w00 = pack2(sWf[k0 * 384 + c]);
            const u64 w01 = pack2(sWf[k0 * 384 + 128 + c]);
            const u64 w02 = pack2(sWf[k0 * 384 + 256 + c]);
            const u64 w10 = pack2(sWf[(k0 + 1) * 384 + c]);
            const u64 w11 = pack2(sWf[(k0 + 1) * 384 + 128 + c]);
            const u64 w12 = pack2(sWf[(k0 + 1) * 384 + 256 + c]);
            #pragma unroll
            for (int p = 0; p < 8; p++) {
                const ulonglong2 ee = *(const ulonglong2*)&sESp[(p * 10 + kd) * 4];
                fma2(acc[p][0], ee.x, w00);
                fma2(acc[p][1], ee.x, w01);
                fma2(acc[p][2], ee.x, w02);
                fma2(acc[p][0], ee.y, w10);
                fma2(acc[p][1], ee.y, w11);
                fma2(acc[p][2], ee.y, w12);
            }
        }

        // ---- epilogue: fused-gate messages, scalar coalesced REDs ----
        #pragma unroll
        for (int p = 0; p < 8; p++) {
            const float2 gS = unpack2(acc[p][0]);
            const float2 gE = unpack2(acc[p][1]);
            const float2 gN = unpack2(acc[p][2]);
            #pragma unroll
            for (int h = 0; h < 2; h++) {
                const int e = 2 * p + h;
                const float4 mt = sMeta[e];
                const int2 sd = sIdx[e];
                const float cu = mt.w;
                const float fSV = (h ? gS.y : gS.x) * cu;
                const float fEV = (h ? gE.y : gE.x) * cu;
                const float fNS = (h ? gN.y : gN.x) * cu;
                const int src = sd.x, dst = sd.y;

                const float sev = __ldg(&g_sev[(size_t)src * 128 + c]);
                const float cns = __ldg(&g_cns[(size_t)src * 128 + c]);
                const float dv0 = __ldg(&g_dsv[(size_t)src * 384 + c]);
                const float dv1 = __ldg(&g_dsv[(size_t)src * 384 + 128 + c]);
                const float dv2 = __ldg(&g_dsv[(size_t)src * 384 + 256 + c]);
                const float tE = fEV * sev;

                red1(&outS[(size_t)dst * 128 + c], fNS * cns);
                float* ov = &outV[(size_t)dst * 384];
                red1(&ov[c],       fmaf(dv0, fSV, mt.x * tE));
                red1(&ov[128 + c], fmaf(dv1, fSV, mt.y * tE));
                red1(&ov[256 + c], fmaf(dv2, fSV, mt.z * tE));
            }
        }
        __syncthreads();
    }
}

// ---------------------------------------------------------------------------
extern "C" void kernel_launch(void* const* d_in, const int* in_sizes, int n_in,
                              void* d_out, int out_size)
{
    const float* nss           = (const float*)d_in[0];
    const float* nsv           = (const float*)d_in[1];
    const float* edge_state    = (const float*)d_in[2];
    const float* edge_vector   = (const float*)d_in[3];
    const float* edge_distance = (const float*)d_in[4];
    const int*   edges         = (const int*)d_in[5];
    const float* W_filter      = (const float*)d_in[6];
    const float* b_filter      = (const float*)d_in[7];
    const float* W1            = (const float*)d_in[8];
    const float* b1            = (const float*)d_in[9];
    const float* W2            = (const float*)d_in[10];
    const float* b2            = (const float*)d_in[11];
    float* out = (float*)d_out;

    const int smem1 = (8192 + 8192 + 8192) * sizeof(float);   // 96 KB
    cudaFuncSetAttribute(node_mlp, cudaFuncAttributeMaxDynamicSharedMemorySize, smem1);
    node_mlp<<<(NNODES + NB - 1) / NB, 256, smem1>>>(
        (const float4*)nss, (const float4*)nsv, W1, b1, W2, b2, (float4*)out);

    edge_kernel<<<740, 128>>>(edge_state, edge_vector, edge_distance,
                              edges, W_filter, b_filter, out);
}